// round 2
// baseline (speedup 1.0000x reference)
#include <cuda_runtime.h>
#include <cuda_bf16.h>
#include <cstdint>

#define N_NODES 100000
#define F_IN 256
#define CH 16
#define FCN 64

// Scratch: __device__ globals (no allocation allowed). 16B aligned for float4/red.v4.
__device__ __align__(16) float g_h[N_NODES * CH];
__device__ __align__(16) float g_agg[N_NODES * CH];
__device__ int g_idx_is64;   // 1 if edge_index is int64, 0 if int32

// ---------------------------------------------------------------------------
// Kernel 0: probe edge_index dtype.
// If int64 (nonneg, < 2^31): every odd 32-bit word is zero.
// If int32: odd words are random node ids — some nonzero among 8192 w.p. ~1.
// ---------------------------------------------------------------------------
__global__ void k0_detect(const int* __restrict__ ei32, int n_words) {
    __shared__ int any;
    if (threadIdx.x == 0) any = 0;
    __syncthreads();
    int limit = n_words < 8192 ? n_words : 8192;
    for (int i = 1 + 2 * threadIdx.x; i < limit; i += 2 * blockDim.x)
        if (ei32[i] != 0) any = 1;   // benign race: all writers store 1
    __syncthreads();
    if (threadIdx.x == 0) g_idx_is64 = (any == 0) ? 1 : 0;
}

// ---------------------------------------------------------------------------
// Kernel 1: h = x @ w_gcn  (warp per node), and zero g_agg.
// w_gcn [256,16] row-major -> transposed in smem as w_t[c*256 + k] so that
// lanes (consecutive k) read consecutive smem words: conflict-free.
// ---------------------------------------------------------------------------
__global__ void k1_xw(const float* __restrict__ x, const float* __restrict__ w_gcn) {
    __shared__ float w_t[F_IN * CH];
    const int tid = threadIdx.x;
    for (int i = tid; i < F_IN * CH; i += blockDim.x) {
        int k = i >> 4;        // row of w_gcn
        int c = i & 15;        // col
        w_t[c * F_IN + k] = w_gcn[i];
    }
    __syncthreads();

    const int gtid = blockIdx.x * blockDim.x + tid;
    // Zero agg (grid has 3.2M threads; agg has 1.6M elements)
    if (gtid < N_NODES * CH) g_agg[gtid] = 0.0f;

    const int warp = gtid >> 5;
    const int lane = tid & 31;
    if (warp >= N_NODES) return;

    const float* __restrict__ xr = x + (size_t)warp * F_IN;
    float acc[CH];
#pragma unroll
    for (int c = 0; c < CH; c++) acc[c] = 0.0f;

#pragma unroll
    for (int i = 0; i < F_IN / 32; i++) {
        float xv = xr[i * 32 + lane];          // coalesced: lanes consecutive
#pragma unroll
        for (int c = 0; c < CH; c++)
            acc[c] += xv * w_t[c * F_IN + i * 32 + lane];  // conflict-free LDS
    }

    // Warp-reduce each channel; lane c keeps channel c's total.
    float mine = 0.0f;
#pragma unroll
    for (int c = 0; c < CH; c++) {
        float v = acc[c];
#pragma unroll
        for (int o = 16; o > 0; o >>= 1)
            v += __shfl_xor_sync(0xFFFFFFFFu, v, o);
        if (lane == c) mine = v;
    }
    if (lane < CH) g_h[(size_t)warp * CH + lane] = mine;
}

// ---------------------------------------------------------------------------
// Kernel 2: edge gather + scatter-add.
// 4 threads per edge; each handles one float4 chunk of the 16-ch row.
// Gather of h row is fully coalesced (4 consecutive lanes -> 64B contiguous).
// Scatter via red.global.add.v4.f32 (no-return vector reduction, sm_90+).
// Index dtype (int32 vs int64) selected by g_idx_is64 (uniform branch).
// ---------------------------------------------------------------------------
__global__ void k2_edges(const int* __restrict__ ei32,
                         const float* __restrict__ ew, int E) {
    long long t = (long long)blockIdx.x * blockDim.x + threadIdx.x;
    int e = (int)(t >> 2);
    int j = (int)(t & 3);
    if (e >= E) return;

    const int is64 = g_idx_is64;
    int src, dst;
    if (is64) {
        // int64 little-endian, values < 2^31: low word holds the value
        src = ei32[(size_t)2 * e];
        dst = ei32[(size_t)2 * (E + e)];
    } else {
        src = ei32[e];
        dst = ei32[(size_t)E + e];
    }
    float w = ew[e];

    const float4 hv = *(const float4*)(g_h + (size_t)src * CH + j * 4);
    float mx = hv.x * w, my = hv.y * w, mz = hv.z * w, mw = hv.w * w;
    float* p = g_agg + (size_t)dst * CH + j * 4;
    asm volatile("red.global.add.v4.f32 [%0], {%1, %2, %3, %4};"
                 :: "l"(p), "f"(mx), "f"(my), "f"(mz), "f"(mw)
                 : "memory");
}

// ---------------------------------------------------------------------------
// Kernel 3: per-node FCN head.
// out[n] = (relu(relu(agg[n]) @ w0 + b0)) @ w1 + b1
// w0/w1/b0/b1 in smem; all threads read the same element each step -> broadcast.
// ---------------------------------------------------------------------------
__global__ void k3_head(const float* __restrict__ w0, const float* __restrict__ b0,
                        const float* __restrict__ w1, const float* __restrict__ b1,
                        float* __restrict__ out) {
    __shared__ float s_w0[CH * FCN];
    __shared__ float s_w1[FCN];
    __shared__ float s_b0[FCN];
    __shared__ float s_b1;
    const int tid = threadIdx.x;
    for (int i = tid; i < CH * FCN; i += blockDim.x) s_w0[i] = w0[i];
    for (int i = tid; i < FCN; i += blockDim.x) { s_w1[i] = w1[i]; s_b0[i] = b0[i]; }
    if (tid == 0) s_b1 = b1[0];
    __syncthreads();

    const int n = blockIdx.x * blockDim.x + tid;
    if (n >= N_NODES) return;

    float a[CH];
    const float4* ap = (const float4*)(g_agg + (size_t)n * CH);
#pragma unroll
    for (int q = 0; q < 4; q++) {
        float4 v = ap[q];
        a[q * 4 + 0] = fmaxf(v.x, 0.0f);
        a[q * 4 + 1] = fmaxf(v.y, 0.0f);
        a[q * 4 + 2] = fmaxf(v.z, 0.0f);
        a[q * 4 + 3] = fmaxf(v.w, 0.0f);
    }

    float o2 = s_b1;
#pragma unroll 4
    for (int f = 0; f < FCN; f++) {
        float o1 = s_b0[f];
#pragma unroll
        for (int c = 0; c < CH; c++)
            o1 += a[c] * s_w0[c * FCN + f];
        o1 = fmaxf(o1, 0.0f);
        o2 += o1 * s_w1[f];
    }
    out[n] = o2;
}

// ---------------------------------------------------------------------------
// Launcher. Inputs identified by element count (robust to ordering):
//   x: 25,600,000   edge_index: 6,400,000   edge_w: 3,200,000
//   w_gcn: 4096     w0: 1024   b0: 64 (first 64)    w1: 64 (second 64)   b1: 1
// ---------------------------------------------------------------------------
extern "C" void kernel_launch(void* const* d_in, const int* in_sizes, int n_in,
                              void* d_out, int out_size) {
    const float* x = nullptr;
    const int* ei = nullptr;
    const float* ew = nullptr;
    const float* wg = nullptr;
    const float* w0 = nullptr;
    const float* b0 = nullptr;
    const float* w1 = nullptr;
    const float* b1 = nullptr;
    int E = 0;
    int seen64 = 0;

    for (int i = 0; i < n_in; i++) {
        int s = in_sizes[i];
        if (s == N_NODES * F_IN)      x  = (const float*)d_in[i];
        else if (s == 6400000)        { ei = (const int*)d_in[i]; E = s / 2; }
        else if (s == 3200000)        ew = (const float*)d_in[i];
        else if (s == F_IN * CH)      wg = (const float*)d_in[i];
        else if (s == CH * FCN)       w0 = (const float*)d_in[i];
        else if (s == FCN)            { if (seen64++ == 0) b0 = (const float*)d_in[i];
                                        else               w1 = (const float*)d_in[i]; }
        else if (s == 1)              b1 = (const float*)d_in[i];
    }

    float* out = (float*)d_out;

    // K0: dtype probe (scan first 8192 int32 words of edge_index)
    k0_detect<<<1, 256>>>(ei, 2 * E);

    // K1: warp per node (+ zero agg)
    {
        int threads = 256;
        int blocks = (N_NODES * 32 + threads - 1) / threads;  // 12500
        k1_xw<<<blocks, threads>>>(x, wg);
    }
    // K2: 4 threads per edge
    {
        long long total = (long long)E * 4;
        int threads = 256;
        int blocks = (int)((total + threads - 1) / threads);
        k2_edges<<<blocks, threads>>>(ei, ew, E);
    }
    // K3: thread per node
    {
        int threads = 128;
        int blocks = (N_NODES + threads - 1) / threads;
        k3_head<<<blocks, threads>>>(w0, b0, w1, b1, out);
    }
}

// round 3
// speedup vs baseline: 1.0368x; 1.0368x over previous
#include <cuda_runtime.h>
#include <cuda_bf16.h>
#include <cstdint>

#define N_NODES 100000
#define F_IN 256
#define CH 16
#define FCN 64
#define NREP 4   // accumulator replicas to cut atomic contention

// Scratch: __device__ globals (no allocation allowed). 16B aligned for float4/red.v4.
__device__ __align__(16) float g_h[N_NODES * CH];
__device__ __align__(16) float g_agg[NREP * N_NODES * CH];
__device__ int g_idx_is64;   // 1 if edge_index is int64, 0 if int32

// ---------------------------------------------------------------------------
// Kernel 0: probe edge_index dtype.
// int64 (nonneg < 2^31): every odd 32-bit word is zero.
// int32: odd words are random node ids -> some nonzero among 8192 w.p. ~1.
// ---------------------------------------------------------------------------
__global__ void k0_detect(const int* __restrict__ ei32, int n_words) {
    __shared__ int any;
    if (threadIdx.x == 0) any = 0;
    __syncthreads();
    int limit = n_words < 8192 ? n_words : 8192;
    for (int i = 1 + 2 * threadIdx.x; i < limit; i += 2 * blockDim.x)
        if (ei32[i] != 0) any = 1;   // benign race: all writers store 1
    __syncthreads();
    if (threadIdx.x == 0) g_idx_is64 = (any == 0) ? 1 : 0;
}

// ---------------------------------------------------------------------------
// Kernel 1: h = x @ w_gcn  (warp per node), and zero all agg replicas.
// w_gcn [256,16] transposed in smem: lanes hit consecutive words, no conflicts.
// ---------------------------------------------------------------------------
__global__ void k1_xw(const float* __restrict__ x, const float* __restrict__ w_gcn) {
    __shared__ float w_t[F_IN * CH];
    const int tid = threadIdx.x;
    for (int i = tid; i < F_IN * CH; i += blockDim.x) {
        int k = i >> 4;
        int c = i & 15;
        w_t[c * F_IN + k] = w_gcn[i];
    }
    __syncthreads();

    const int gtid = blockIdx.x * blockDim.x + tid;
    // Zero agg replicas: NREP*1.6M floats = 1.6M float4 (grid has 3.2M threads)
    if (gtid < (NREP * N_NODES * CH) / 4)
        ((float4*)g_agg)[gtid] = make_float4(0.f, 0.f, 0.f, 0.f);

    const int warp = gtid >> 5;
    const int lane = tid & 31;
    if (warp >= N_NODES) return;

    const float* __restrict__ xr = x + (size_t)warp * F_IN;
    float acc[CH];
#pragma unroll
    for (int c = 0; c < CH; c++) acc[c] = 0.0f;

#pragma unroll
    for (int i = 0; i < F_IN / 32; i++) {
        float xv = xr[i * 32 + lane];          // coalesced
#pragma unroll
        for (int c = 0; c < CH; c++)
            acc[c] += xv * w_t[c * F_IN + i * 32 + lane];  // conflict-free LDS
    }

    float mine = 0.0f;
#pragma unroll
    for (int c = 0; c < CH; c++) {
        float v = acc[c];
#pragma unroll
        for (int o = 16; o > 0; o >>= 1)
            v += __shfl_xor_sync(0xFFFFFFFFu, v, o);
        if (lane == c) mine = v;
    }
    if (lane < CH) g_h[(size_t)warp * CH + lane] = mine;
}

// ---------------------------------------------------------------------------
// Kernel 2: edge gather + scatter-add.
// 4 threads per edge; each handles one float4 chunk of the 16-ch row.
// Gather of h row is fully coalesced (4 lanes -> 64B contiguous).
// Scatter via red.global.add.v4.f32 into replica (e & 3): per-address
// collision degree drops 4x vs single accumulator.
// ---------------------------------------------------------------------------
__global__ void k2_edges(const int* __restrict__ ei32,
                         const float* __restrict__ ew, int E) {
    long long t = (long long)blockIdx.x * blockDim.x + threadIdx.x;
    int e = (int)(t >> 2);
    int j = (int)(t & 3);
    if (e >= E) return;

    const int is64 = g_idx_is64;
    int src, dst;
    if (is64) {
        src = ei32[(size_t)2 * e];
        dst = ei32[(size_t)2 * (E + e)];
    } else {
        src = ei32[e];
        dst = ei32[(size_t)E + e];
    }
    float w = ew[e];

    const float4 hv = *(const float4*)(g_h + (size_t)src * CH + j * 4);
    float mx = hv.x * w, my = hv.y * w, mz = hv.z * w, mw = hv.w * w;
    int rep = e & (NREP - 1);
    float* p = g_agg + (size_t)rep * (N_NODES * CH) + (size_t)dst * CH + j * 4;
    asm volatile("red.global.add.v4.f32 [%0], {%1, %2, %3, %4};"
                 :: "l"(p), "f"(mx), "f"(my), "f"(mz), "f"(mw)
                 : "memory");
}

// ---------------------------------------------------------------------------
// Kernel 3: per-node FCN head (sums the NREP agg replicas first).
// w0 stored transposed [f][c] in smem, read as float4 (LDS.128):
// per-thread issue count ~1300 vs ~2050 with scalar LDS.
// ---------------------------------------------------------------------------
__global__ void k3_head(const float* __restrict__ w0, const float* __restrict__ b0,
                        const float* __restrict__ w1, const float* __restrict__ b1,
                        float* __restrict__ out) {
    __shared__ float s_w0t[FCN * CH];   // [f][c]
    __shared__ float s_w1[FCN];
    __shared__ float s_b0[FCN];
    __shared__ float s_b1;
    const int tid = threadIdx.x;
    for (int i = tid; i < CH * FCN; i += blockDim.x) {
        int c = i / FCN, f = i % FCN;
        s_w0t[f * CH + c] = w0[i];
    }
    for (int i = tid; i < FCN; i += blockDim.x) { s_w1[i] = w1[i]; s_b0[i] = b0[i]; }
    if (tid == 0) s_b1 = b1[0];
    __syncthreads();

    const int n = blockIdx.x * blockDim.x + tid;
    if (n >= N_NODES) return;

    // Sum replicas, then relu.
    float4 a4[4];
#pragma unroll
    for (int q = 0; q < 4; q++) a4[q] = make_float4(0.f, 0.f, 0.f, 0.f);
#pragma unroll
    for (int r = 0; r < NREP; r++) {
        const float4* ap = (const float4*)(g_agg + (size_t)r * (N_NODES * CH)
                                                 + (size_t)n * CH);
#pragma unroll
        for (int q = 0; q < 4; q++) {
            float4 v = ap[q];
            a4[q].x += v.x; a4[q].y += v.y; a4[q].z += v.z; a4[q].w += v.w;
        }
    }
#pragma unroll
    for (int q = 0; q < 4; q++) {
        a4[q].x = fmaxf(a4[q].x, 0.f); a4[q].y = fmaxf(a4[q].y, 0.f);
        a4[q].z = fmaxf(a4[q].z, 0.f); a4[q].w = fmaxf(a4[q].w, 0.f);
    }

    const float4* w0t4 = (const float4*)s_w0t;  // [f][c/4]
    float o2 = s_b1;
#pragma unroll 4
    for (int f = 0; f < FCN; f++) {
        float o1 = s_b0[f];
#pragma unroll
        for (int q = 0; q < 4; q++) {
            float4 w4 = w0t4[f * 4 + q];        // LDS.128, broadcast
            o1 += a4[q].x * w4.x + a4[q].y * w4.y
                + a4[q].z * w4.z + a4[q].w * w4.w;
        }
        o1 = fmaxf(o1, 0.0f);
        o2 += o1 * s_w1[f];
    }
    out[n] = o2;
}

// ---------------------------------------------------------------------------
// Launcher. Inputs identified by element count (robust to ordering):
//   x: 25,600,000   edge_index: 6,400,000   edge_w: 3,200,000
//   w_gcn: 4096     w0: 1024   b0: 64 (first)   w1: 64 (second)   b1: 1
// ---------------------------------------------------------------------------
extern "C" void kernel_launch(void* const* d_in, const int* in_sizes, int n_in,
                              void* d_out, int out_size) {
    const float* x = nullptr;
    const int* ei = nullptr;
    const float* ew = nullptr;
    const float* wg = nullptr;
    const float* w0 = nullptr;
    const float* b0 = nullptr;
    const float* w1 = nullptr;
    const float* b1 = nullptr;
    int E = 0;
    int seen64 = 0;

    for (int i = 0; i < n_in; i++) {
        int s = in_sizes[i];
        if (s == N_NODES * F_IN)      x  = (const float*)d_in[i];
        else if (s == 6400000)        { ei = (const int*)d_in[i]; E = s / 2; }
        else if (s == 3200000)        ew = (const float*)d_in[i];
        else if (s == F_IN * CH)      wg = (const float*)d_in[i];
        else if (s == CH * FCN)       w0 = (const float*)d_in[i];
        else if (s == FCN)            { if (seen64++ == 0) b0 = (const float*)d_in[i];
                                        else               w1 = (const float*)d_in[i]; }
        else if (s == 1)              b1 = (const float*)d_in[i];
    }

    float* out = (float*)d_out;

    // K0: dtype probe
    k0_detect<<<1, 256>>>(ei, 2 * E);

    // K1: warp per node (+ zero agg replicas)
    {
        int threads = 256;
        int blocks = (N_NODES * 32 + threads - 1) / threads;  // 12500
        k1_xw<<<blocks, threads>>>(x, wg);
    }
    // K2: 4 threads per edge
    {
        long long total = (long long)E * 4;
        int threads = 256;
        int blocks = (int)((total + threads - 1) / threads);
        k2_edges<<<blocks, threads>>>(ei, ew, E);
    }
    // K3: thread per node
    {
        int threads = 128;
        int blocks = (N_NODES + threads - 1) / threads;
        k3_head<<<blocks, threads>>>(w0, b0, w1, b1, out);
    }
}